// round 2
// baseline (speedup 1.0000x reference)
#include <cuda_runtime.h>
#include <cstdint>

// CorrelationAlign: out[b, a*63+c, i, j] = corr[b, (a-31+i)*32 + (c-31+j), i, j]
// when 0 <= a-31+i < 32 and 0 <= c-31+j < 32, else 0.
//
// corr : float[16][1024][32][32]  (b, p*32+q, i, j)
// out  : float[16][3969][32][32]  (b, a*63+c, i, j)
//
// Block = (b, a, i). p = a-31+i is block-constant.
//  - load 32x32 (q,j) slab coalesced (32 rows of 128B) into padded smem
//  - write 63 output rows of 128B, shifted-gather from smem, zero-filled.

static constexpr int Bn   = 16;
static constexpr int Hh   = 32;   // h == w == 32
static constexpr int HWo  = 63;   // 2*h-1
static constexpr int THREADS = 256;

__global__ __launch_bounds__(THREADS, 8)
void corr_align_kernel(const float* __restrict__ corr, float* __restrict__ out)
{
    const int bx = blockIdx.x;
    const int i  = bx & 31;              // 0..31
    const int a  = (bx >> 5) % HWo;      // 0..62
    const int b  = bx / (HWo * Hh);      // 0..15

    const int  p      = a - (Hh - 1) + i;
    const bool pvalid = (p >= 0) && (p < Hh);

    __shared__ float tile[Hh * 33];      // pad 32->33: conflict-free shifted reads

    const int t = threadIdx.x;

    if (pvalid) {
        // 256 threads load 1024 floats as 256 float4s.
        const int q  = t >> 3;           // 0..31
        const int j4 = (t & 7) << 2;     // 0,4,...,28
        const size_t src_off = ((size_t)b << 20)            // b * 1024*1024
                             + (size_t)(p * Hh + q) * 1024  // pq * 1024
                             + (size_t)i * 32 + j4;
        const float4 v = __ldcs((const float4*)(corr + src_off));
        float* drow = &tile[q * 33 + j4];
        drow[0] = v.x; drow[1] = v.y; drow[2] = v.z; drow[3] = v.w;
    }
    __syncthreads();

    float* obase = out + (size_t)b * (HWo * HWo) * 1024
                       + (size_t)a * HWo * 1024
                       + (size_t)i * 32;

    // 63 rows (c) x 8 float4 (j4) = 504 stores over 2 iterations of 256 threads.
    #pragma unroll
    for (int iter = 0; iter < 2; ++iter) {
        const int idx = t + iter * THREADS;
        if (idx < HWo * 8) {
            const int c  = idx >> 3;         // 0..62
            const int j4 = (idx & 7) << 2;   // 0,4,...,28
            float r[4];
            #pragma unroll
            for (int k = 0; k < 4; ++k) {
                const int j = j4 + k;
                const int q = c - (Hh - 1) + j;
                r[k] = (pvalid && q >= 0 && q < Hh) ? tile[q * 33 + j] : 0.0f;
            }
            float4 v; v.x = r[0]; v.y = r[1]; v.z = r[2]; v.w = r[3];
            __stcs((float4*)(obase + (size_t)c * 1024 + j4), v);
        }
    }
}

extern "C" void kernel_launch(void* const* d_in, const int* in_sizes, int n_in,
                              void* d_out, int out_size)
{
    const float* corr = (const float*)d_in[0];
    float*       out  = (float*)d_out;
    (void)in_sizes; (void)n_in; (void)out_size;

    const int grid = Bn * HWo * Hh;      // 16 * 63 * 32 = 32256
    corr_align_kernel<<<grid, THREADS>>>(corr, out);
}